// round 10
// baseline (speedup 1.0000x reference)
#include <cuda_runtime.h>
#include <cuda_bf16.h>
#include <cuda_fp16.h>
#include <cstdint>

// Problem constants
#define BB 8
#define CC 256
#define HH 128
#define WW 128
#define ND 64

// ---------------------------------------------------------------------------
// Scratch (__device__ globals; no runtime allocation)
// ---------------------------------------------------------------------------
__device__ float g_style[BB * CC];
__device__ __align__(256) __half g_Af[BB * 9 * CC * CC];            // [b][tap][oc][i]
__device__ __align__(256) __half g_Ff[(size_t)BB * HH * WW * CC];   // [b][y][x][c]

// ---------------------------------------------------------------------------
// PTX helpers (sm_80-era; compile on compute_103)
// ---------------------------------------------------------------------------
__device__ __forceinline__ uint32_t smem_u32(const void* p) {
    uint32_t a;
    asm("{ .reg .u64 t; cvta.to.shared.u64 t, %1; cvt.u32.u64 %0, t; }" : "=r"(a) : "l"(p));
    return a;
}
__device__ __forceinline__ void cpa16(uint32_t dst, const void* src, uint32_t bytes) {
    asm volatile("cp.async.cg.shared.global [%0], [%1], 16, %2;"
                 :: "r"(dst), "l"(src), "r"(bytes) : "memory");
}
__device__ __forceinline__ void cpa_commit() {
    asm volatile("cp.async.commit_group;" ::: "memory");
}
__device__ __forceinline__ void cpa_wait2() {
    asm volatile("cp.async.wait_group 2;" ::: "memory");
}
__device__ __forceinline__ uint32_t swz(uint32_t off) { return off ^ ((off >> 3) & 0x70); }

__device__ __forceinline__ void ldsm_x4(uint32_t& r0, uint32_t& r1, uint32_t& r2, uint32_t& r3,
                                        uint32_t addr) {
    asm volatile("ldmatrix.sync.aligned.m8n8.x4.shared.b16 {%0,%1,%2,%3}, [%4];"
                 : "=r"(r0), "=r"(r1), "=r"(r2), "=r"(r3) : "r"(addr));
}
__device__ __forceinline__ void mma_fp16(float* d, const uint32_t* a, const uint32_t* b) {
    asm volatile(
        "mma.sync.aligned.m16n8k16.row.col.f32.f16.f16.f32 "
        "{%0,%1,%2,%3}, {%4,%5,%6,%7}, {%8,%9}, {%0,%1,%2,%3};"
        : "+f"(d[0]), "+f"(d[1]), "+f"(d[2]), "+f"(d[3])
        : "r"(a[0]), "r"(a[1]), "r"(a[2]), "r"(a[3]), "r"(b[0]), "r"(b[1]));
}

// ---------------------------------------------------------------------------
// Kernel 0: style
// ---------------------------------------------------------------------------
__global__ void style_kernel(const float* __restrict__ nf,
                             const float* __restrict__ mw,
                             const float* __restrict__ mb) {
    int b = blockIdx.x, c = threadIdx.x;
    const float* nfb = nf + b * ND;
    const float* mwc = mw + c * ND;
    float s = 0.f;
#pragma unroll
    for (int d = 0; d < ND; ++d) s += nfb[d] * mwc[d];
    g_style[b * CC + c] = s + mb[c];
}

// ---------------------------------------------------------------------------
// Kernel 1: modulate + demod weights -> fp16, layout [b][tap][oc][i]
// ---------------------------------------------------------------------------
__global__ void modw_kernel(const float* __restrict__ weight) {
    int o = blockIdx.x, b = blockIdx.y, i = threadIdx.x;
    const float scale = 1.0f / 48.0f;
    float s = g_style[b * CC + i] * scale;
    const float* wp = weight + (o * CC + i) * 9;
    float v[9];
    float sq = 0.f;
#pragma unroll
    for (int k = 0; k < 9; ++k) { v[k] = wp[k] * s; sq += v[k] * v[k]; }

    __shared__ float red[8];
#pragma unroll
    for (int off = 16; off; off >>= 1) sq += __shfl_xor_sync(0xffffffffu, sq, off);
    if ((threadIdx.x & 31) == 0) red[threadIdx.x >> 5] = sq;
    __syncthreads();
    if (threadIdx.x < 8) {
        float t = red[threadIdx.x];
#pragma unroll
        for (int off = 4; off; off >>= 1) t += __shfl_xor_sync(0xffu, t, off);
        if (threadIdx.x == 0) red[0] = t;
    }
    __syncthreads();
    float demod = rsqrtf(red[0] + 1e-8f);
#pragma unroll
    for (int k = 0; k < 9; ++k) {
        size_t idx = ((size_t)((b * 9 + k) * CC) + o) * CC + i;
        g_Af[idx] = __float2half(v[k] * demod);
    }
}

// ---------------------------------------------------------------------------
// Kernel 2: fea NCHW -> [b][y][x][c] fp16
// ---------------------------------------------------------------------------
__global__ __launch_bounds__(256)
void tsplit_kernel(const float* __restrict__ fea) {
    int y = blockIdx.x, b = blockIdx.y;
    __shared__ float t[64][129];
    for (int cc = 0; cc < 4; ++cc) {
#pragma unroll
        for (int k = 0; k < 32; ++k) {
            int idx = threadIdx.x + k * 256;
            int cs = idx >> 7, x = idx & 127;
            t[cs][x] = fea[(((size_t)(b * CC + cc * 64 + cs)) * HH + y) * WW + x];
        }
        __syncthreads();
#pragma unroll
        for (int k = 0; k < 32; ++k) {
            int idx = threadIdx.x + k * 256;
            int c2 = idx & 63, x = idx >> 6;
            size_t o = ((size_t)((b * HH + y) * WW + x)) * CC + cc * 64 + c2;
            g_Ff[o] = __float2half(t[c2][x]);
        }
        __syncthreads();
    }
}

// ---------------------------------------------------------------------------
// Kernel 3: implicit-GEMM conv via mma.sync, fp16 operands, f32 accum.
// grid (y=128, mt=2, b=8); CTA = 128 oc x 128 px; 256 threads, 8 warps
// (4M x 2N, warp tile 32x64). K-loop: 36 steps (9 taps x 4 ch-chunks of 64);
// 4-stage cp.async ring, stage = A(16K) + B(16K) = 32KB, SW128 rows of 128B.
// Fragment double-buffering inside the kk loop keeps HMMA fed.
// ---------------------------------------------------------------------------
#define NSTAGE 4
#define STAGE_BYTES 32768
#define SMEM_TOTAL (NSTAGE * STAGE_BYTES)

__global__ __launch_bounds__(256, 1)
void gemm_kernel(float* __restrict__ out) {
    extern __shared__ char smem[];
    const uint32_t sb = smem_u32(smem);
    const int tid  = threadIdx.x;
    const int lane = tid & 31;
    const int wid  = tid >> 5;
    const int warpM = wid >> 1;   // 0..3 (32 oc rows each)
    const int warpN = wid & 1;    // 0..1 (64 px cols each)
    const int y = blockIdx.x, mt = blockIdx.y, b = blockIdx.z;

    // ---- producer assignment ----
    // threads 0-127: A row tid (128B = 8 cpa16); threads 128-255: B row tid-128.
    const bool isA = tid < 128;
    const int row = tid & 127;
    const size_t aRowBase = ((size_t)(b * 9) * CC + mt * 128 + row) * CC;

    auto issue = [&](int step, int buf) {
        const int tap = step >> 2, ck = step & 3;
        const uint32_t stg = sb + (uint32_t)buf * STAGE_BYTES;
        if (isA) {
            const __half* srcA = g_Af + aRowBase + (size_t)tap * CC * CC + ck * 64;
#pragma unroll
            for (int j = 0; j < 8; ++j)
                cpa16(stg + swz((uint32_t)row * 128u + j * 16u), srcA + j * 8, 16u);
        } else {
            const int yy = y + tap / 3 - 1;
            const int xx = row + tap % 3 - 1;
            const bool bv = (yy >= 0 && yy < HH && xx >= 0 && xx < WW);
            const size_t boff = ((size_t)((b * HH + (bv ? yy : 0)) * WW + (bv ? xx : 0))) * CC
                                + ck * 64;
            const __half* srcB = g_Ff + boff;
            const uint32_t bsz = bv ? 16u : 0u;
#pragma unroll
            for (int j = 0; j < 8; ++j)
                cpa16(stg + 16384u + swz((uint32_t)row * 128u + j * 16u), srcB + j * 8, bsz);
        }
    };

    // ---- consumer address bases (pre-swizzle offsets within a stage) ----
    // A (x4): row = warpM*32 + m*16 + (lane&15); col16B = (lane>>4)
    const uint32_t aRowB = ((uint32_t)warpM * 32u + (lane & 15)) * 128u + ((lane >> 4) * 16u);
    // B (x4, 2 n-tiles per load): row = warpN*64 + np*16 + (lane>>4)*8 + (lane&7)
    const uint32_t bRowB = ((uint32_t)warpN * 64u + (lane >> 4) * 8u + (lane & 7)) * 128u
                           + (((lane >> 3) & 1) * 16u);

    float acc[2][8][4];
#pragma unroll
    for (int m = 0; m < 2; ++m)
#pragma unroll
        for (int n = 0; n < 8; ++n)
#pragma unroll
            for (int i = 0; i < 4; ++i) acc[m][n][i] = 0.f;

    // double-buffered fragments
    uint32_t A[2][2][4], B[2][4][4];

    auto load_frags = [&](uint32_t stg, int kk, int fb) {
#pragma unroll
        for (int m = 0; m < 2; ++m) {
            const uint32_t off = swz(aRowB + (uint32_t)m * 2048u + (uint32_t)kk * 32u);
            ldsm_x4(A[fb][m][0], A[fb][m][1], A[fb][m][2], A[fb][m][3], stg + off);
        }
#pragma unroll
        for (int np = 0; np < 4; ++np) {
            const uint32_t off = swz(bRowB + (uint32_t)np * 2048u + (uint32_t)kk * 32u);
            ldsm_x4(B[fb][np][0], B[fb][np][1], B[fb][np][2], B[fb][np][3],
                    stg + 16384u + off);
        }
    };

    // prologue: stages 0,1,2 in flight
    issue(0, 0); cpa_commit();
    issue(1, 1); cpa_commit();
    issue(2, 2); cpa_commit();

#pragma unroll 1
    for (int s = 0; s < 36; ++s) {
        cpa_wait2();          // stage s copies complete (this thread)
        __syncthreads();      // all threads done with step s-1 AND stage s visible
        // producer writes buffer (s+3)%4 == (s-1)%4: safe only after the barrier
        if (s + 3 < 36) issue(s + 3, (s + 3) & 3);
        cpa_commit();

        const uint32_t stg = sb + (uint32_t)(s & 3) * STAGE_BYTES;

        load_frags(stg, 0, 0);
#pragma unroll
        for (int kk = 0; kk < 4; ++kk) {
            const int cur = kk & 1;
            if (kk < 3) load_frags(stg, kk + 1, cur ^ 1);
#pragma unroll
            for (int m = 0; m < 2; ++m)
#pragma unroll
                for (int n = 0; n < 8; ++n)
                    mma_fp16(acc[m][n], A[cur][m], &B[cur][n >> 1][(n & 1) * 2]);
        }
    }

    // ---- epilogue ----
    const int r0 = mt * 128 + warpM * 32 + (lane >> 2);
    const int xc = warpN * 64 + (lane & 3) * 2;
#pragma unroll
    for (int m = 0; m < 2; ++m) {
#pragma unroll
        for (int n = 0; n < 8; ++n) {
            float* p0 = out + (((size_t)(b * CC + r0 + m * 16) * HH + y) * WW) + xc + n * 8;
            float* p1 = p0 + (size_t)8 * HH * WW;
            *(float2*)p0 = make_float2(acc[m][n][0], acc[m][n][1]);
            *(float2*)p1 = make_float2(acc[m][n][2], acc[m][n][3]);
        }
    }
}

// ---------------------------------------------------------------------------
extern "C" void kernel_launch(void* const* d_in, const int* in_sizes, int n_in,
                              void* d_out, int out_size) {
    const float* fea    = (const float*)d_in[0];
    const float* nf     = (const float*)d_in[1];
    const float* mw     = (const float*)d_in[2];
    const float* mb     = (const float*)d_in[3];
    const float* weight = (const float*)d_in[4];
    float* out = (float*)d_out;

    cudaFuncSetAttribute(gemm_kernel, cudaFuncAttributeMaxDynamicSharedMemorySize, SMEM_TOTAL);

    style_kernel<<<BB, CC>>>(nf, mw, mb);
    modw_kernel<<<dim3(CC, BB), CC>>>(weight);
    tsplit_kernel<<<dim3(HH, BB), 256>>>(fea);
    gemm_kernel<<<dim3(HH, 2, BB), 256, SMEM_TOTAL>>>(out);
}

// round 11
// speedup vs baseline: 1.0842x; 1.0842x over previous
#include <cuda_runtime.h>
#include <cuda_bf16.h>
#include <cuda_fp16.h>
#include <cstdint>

// Problem constants
#define BB 8
#define CC 256
#define HH 128
#define WW 128
#define ND 64

// ---------------------------------------------------------------------------
// Scratch (__device__ globals; no runtime allocation)
// ---------------------------------------------------------------------------
__device__ float g_style[BB * CC];
__device__ __align__(256) __half g_Af[BB * 9 * CC * CC];            // [b][tap][oc][i]
__device__ __align__(256) __half g_Ff[(size_t)BB * HH * WW * CC];   // [b][y][x][c]

// ---------------------------------------------------------------------------
// PTX helpers (sm_80-era; compile on compute_103)
// ---------------------------------------------------------------------------
__device__ __forceinline__ uint32_t smem_u32(const void* p) {
    uint32_t a;
    asm("{ .reg .u64 t; cvta.to.shared.u64 t, %1; cvt.u32.u64 %0, t; }" : "=r"(a) : "l"(p));
    return a;
}
__device__ __forceinline__ void cpa16(uint32_t dst, const void* src, uint32_t bytes) {
    asm volatile("cp.async.cg.shared.global [%0], [%1], 16, %2;"
                 :: "r"(dst), "l"(src), "r"(bytes) : "memory");
}
__device__ __forceinline__ void cpa_commit() {
    asm volatile("cp.async.commit_group;" ::: "memory");
}
__device__ __forceinline__ void cpa_wait1() {
    asm volatile("cp.async.wait_group 1;" ::: "memory");
}
__device__ __forceinline__ uint32_t swz(uint32_t off) { return off ^ ((off >> 3) & 0x70); }

__device__ __forceinline__ void ldsm_x4(uint32_t& r0, uint32_t& r1, uint32_t& r2, uint32_t& r3,
                                        uint32_t addr) {
    asm volatile("ldmatrix.sync.aligned.m8n8.x4.shared.b16 {%0,%1,%2,%3}, [%4];"
                 : "=r"(r0), "=r"(r1), "=r"(r2), "=r"(r3) : "r"(addr));
}
__device__ __forceinline__ void mma_fp16(float* d, const uint32_t* a, const uint32_t* b) {
    asm volatile(
        "mma.sync.aligned.m16n8k16.row.col.f32.f16.f16.f32 "
        "{%0,%1,%2,%3}, {%4,%5,%6,%7}, {%8,%9}, {%0,%1,%2,%3};"
        : "+f"(d[0]), "+f"(d[1]), "+f"(d[2]), "+f"(d[3])
        : "r"(a[0]), "r"(a[1]), "r"(a[2]), "r"(a[3]), "r"(b[0]), "r"(b[1]));
}

// ---------------------------------------------------------------------------
// Kernel 0: style
// ---------------------------------------------------------------------------
__global__ void style_kernel(const float* __restrict__ nf,
                             const float* __restrict__ mw,
                             const float* __restrict__ mb) {
    int b = blockIdx.x, c = threadIdx.x;
    const float* nfb = nf + b * ND;
    const float* mwc = mw + c * ND;
    float s = 0.f;
#pragma unroll
    for (int d = 0; d < ND; ++d) s += nfb[d] * mwc[d];
    g_style[b * CC + c] = s + mb[c];
}

// ---------------------------------------------------------------------------
// Kernel 1: modulate + demod weights -> fp16, layout [b][tap][oc][i]
// ---------------------------------------------------------------------------
__global__ void modw_kernel(const float* __restrict__ weight) {
    int o = blockIdx.x, b = blockIdx.y, i = threadIdx.x;
    const float scale = 1.0f / 48.0f;
    float s = g_style[b * CC + i] * scale;
    const float* wp = weight + (o * CC + i) * 9;
    float v[9];
    float sq = 0.f;
#pragma unroll
    for (int k = 0; k < 9; ++k) { v[k] = wp[k] * s; sq += v[k] * v[k]; }

    __shared__ float red[8];
#pragma unroll
    for (int off = 16; off; off >>= 1) sq += __shfl_xor_sync(0xffffffffu, sq, off);
    if ((threadIdx.x & 31) == 0) red[threadIdx.x >> 5] = sq;
    __syncthreads();
    if (threadIdx.x < 8) {
        float t = red[threadIdx.x];
#pragma unroll
        for (int off = 4; off; off >>= 1) t += __shfl_xor_sync(0xffu, t, off);
        if (threadIdx.x == 0) red[0] = t;
    }
    __syncthreads();
    float demod = rsqrtf(red[0] + 1e-8f);
#pragma unroll
    for (int k = 0; k < 9; ++k) {
        size_t idx = ((size_t)((b * 9 + k) * CC) + o) * CC + i;
        g_Af[idx] = __float2half(v[k] * demod);
    }
}

// ---------------------------------------------------------------------------
// Kernel 2: fea NCHW -> [b][y][x][c] fp16
// ---------------------------------------------------------------------------
__global__ __launch_bounds__(256)
void tsplit_kernel(const float* __restrict__ fea) {
    int y = blockIdx.x, b = blockIdx.y;
    __shared__ float t[64][129];
    for (int cc = 0; cc < 4; ++cc) {
#pragma unroll
        for (int k = 0; k < 32; ++k) {
            int idx = threadIdx.x + k * 256;
            int cs = idx >> 7, x = idx & 127;
            t[cs][x] = fea[(((size_t)(b * CC + cc * 64 + cs)) * HH + y) * WW + x];
        }
        __syncthreads();
#pragma unroll
        for (int k = 0; k < 32; ++k) {
            int idx = threadIdx.x + k * 256;
            int c2 = idx & 63, x = idx >> 6;
            size_t o = ((size_t)((b * HH + y) * WW + x)) * CC + cc * 64 + c2;
            g_Ff[o] = __float2half(t[c2][x]);
        }
        __syncthreads();
    }
}

// ---------------------------------------------------------------------------
// Kernel 3: implicit-GEMM conv via mma.sync, fp16 operands, f32 accum.
// grid (y=128, mt=2, b=8) = 2048 CTAs; CTA = 128 oc x 128 px; 256 threads,
// 8 warps (4M x 2N, warp tile 32x64). TWO CTAs per SM (independent barriers
// de-phase load/MMA cycles). 36 K-steps; 3-stage ring of 32KB; 1 barrier/step.
// ---------------------------------------------------------------------------
#define NSTAGE 3
#define STAGE_BYTES 32768
#define SMEM_TOTAL (NSTAGE * STAGE_BYTES)

__global__ __launch_bounds__(256, 2)
void gemm_kernel(float* __restrict__ out) {
    extern __shared__ char smem[];
    const uint32_t sb = smem_u32(smem);
    const int tid  = threadIdx.x;
    const int lane = tid & 31;
    const int wid  = tid >> 5;
    const int warpM = wid >> 1;   // 0..3 (32 oc rows each)
    const int warpN = wid & 1;    // 0..1 (64 px cols each)
    const int y = blockIdx.x, mt = blockIdx.y, b = blockIdx.z;

    // ---- producer assignment ----
    // threads 0-127: A row tid (128B = 8 cpa16); threads 128-255: B row tid-128.
    const bool isA = tid < 128;
    const int row = tid & 127;
    const size_t aRowBase = ((size_t)(b * 9) * CC + mt * 128 + row) * CC;

    auto issue = [&](int step, int buf) {
        const int tap = step >> 2, ck = step & 3;
        const uint32_t stg = sb + (uint32_t)buf * STAGE_BYTES;
        if (isA) {
            const __half* srcA = g_Af + aRowBase + (size_t)tap * CC * CC + ck * 64;
#pragma unroll
            for (int j = 0; j < 8; ++j)
                cpa16(stg + swz((uint32_t)row * 128u + j * 16u), srcA + j * 8, 16u);
        } else {
            const int yy = y + tap / 3 - 1;
            const int xx = row + tap % 3 - 1;
            const bool bv = (yy >= 0 && yy < HH && xx >= 0 && xx < WW);
            const size_t boff = ((size_t)((b * HH + (bv ? yy : 0)) * WW + (bv ? xx : 0))) * CC
                                + ck * 64;
            const __half* srcB = g_Ff + boff;
            const uint32_t bsz = bv ? 16u : 0u;
#pragma unroll
            for (int j = 0; j < 8; ++j)
                cpa16(stg + 16384u + swz((uint32_t)row * 128u + j * 16u), srcB + j * 8, bsz);
        }
    };

    // ---- consumer address bases (pre-swizzle offsets within a stage) ----
    // A (x4): row = warpM*32 + m*16 + (lane&15); col16B = (lane>>4)
    const uint32_t aRowB = ((uint32_t)warpM * 32u + (lane & 15)) * 128u + ((lane >> 4) * 16u);
    // B (x4, 2 n-tiles per load): row = warpN*64 + np*16 + (lane>>4)*8 + (lane&7)
    const uint32_t bRowB = ((uint32_t)warpN * 64u + (lane >> 4) * 8u + (lane & 7)) * 128u
                           + (((lane >> 3) & 1) * 16u);

    float acc[2][8][4];
#pragma unroll
    for (int m = 0; m < 2; ++m)
#pragma unroll
        for (int n = 0; n < 8; ++n)
#pragma unroll
            for (int i = 0; i < 4; ++i) acc[m][n][i] = 0.f;

    // prologue: stages 0,1 in flight
    issue(0, 0); cpa_commit();
    issue(1, 1); cpa_commit();

#pragma unroll 1
    for (int s = 0; s < 36; ++s) {
        cpa_wait1();          // this thread's stage-s copies complete
        __syncthreads();      // all threads' copies visible; step s-1 reads done
        // producer writes buffer (s+2)%3 == (s-1)%3: safe only after the barrier
        if (s + 2 < 36) issue(s + 2, (s + 2) % NSTAGE);
        cpa_commit();

        const uint32_t stg = sb + (uint32_t)(s % NSTAGE) * STAGE_BYTES;

#pragma unroll
        for (int kk = 0; kk < 4; ++kk) {
            uint32_t A[2][4], B[4][4];
#pragma unroll
            for (int m = 0; m < 2; ++m) {
                const uint32_t off = swz(aRowB + (uint32_t)m * 2048u + (uint32_t)kk * 32u);
                ldsm_x4(A[m][0], A[m][1], A[m][2], A[m][3], stg + off);
            }
#pragma unroll
            for (int np = 0; np < 4; ++np) {
                const uint32_t off = swz(bRowB + (uint32_t)np * 2048u + (uint32_t)kk * 32u);
                ldsm_x4(B[np][0], B[np][1], B[np][2], B[np][3], stg + 16384u + off);
            }
#pragma unroll
            for (int m = 0; m < 2; ++m)
#pragma unroll
                for (int n = 0; n < 8; ++n)
                    mma_fp16(acc[m][n], A[m], &B[n >> 1][(n & 1) * 2]);
        }
    }

    // ---- epilogue ----
    const int r0 = mt * 128 + warpM * 32 + (lane >> 2);
    const int xc = warpN * 64 + (lane & 3) * 2;
#pragma unroll
    for (int m = 0; m < 2; ++m) {
#pragma unroll
        for (int n = 0; n < 8; ++n) {
            float* p0 = out + (((size_t)(b * CC + r0 + m * 16) * HH + y) * WW) + xc + n * 8;
            float* p1 = p0 + (size_t)8 * HH * WW;
            *(float2*)p0 = make_float2(acc[m][n][0], acc[m][n][1]);
            *(float2*)p1 = make_float2(acc[m][n][2], acc[m][n][3]);
        }
    }
}

// ---------------------------------------------------------------------------
extern "C" void kernel_launch(void* const* d_in, const int* in_sizes, int n_in,
                              void* d_out, int out_size) {
    const float* fea    = (const float*)d_in[0];
    const float* nf     = (const float*)d_in[1];
    const float* mw     = (const float*)d_in[2];
    const float* mb     = (const float*)d_in[3];
    const float* weight = (const float*)d_in[4];
    float* out = (float*)d_out;

    cudaFuncSetAttribute(gemm_kernel, cudaFuncAttributeMaxDynamicSharedMemorySize, SMEM_TOTAL);

    style_kernel<<<BB, CC>>>(nf, mw, mb);
    modw_kernel<<<dim3(CC, BB), CC>>>(weight);
    tsplit_kernel<<<dim3(HH, BB), 256>>>(fea);
    gemm_kernel<<<dim3(HH, 2, BB), 256, SMEM_TOTAL>>>(out);
}

// round 12
// speedup vs baseline: 1.2540x; 1.1566x over previous
#include <cuda_runtime.h>
#include <cuda_bf16.h>
#include <cuda_fp16.h>
#include <cstdint>

// Problem constants
#define BB 8
#define CC 256
#define HH 128
#define WW 128
#define ND 64

// ---------------------------------------------------------------------------
// Scratch (__device__ globals; no runtime allocation)
// ---------------------------------------------------------------------------
__device__ float g_style[BB * CC];
__device__ __align__(256) __half g_Af[BB * 9 * CC * CC];            // [b][tap][oc][i]
__device__ __align__(256) __half g_Ff[(size_t)BB * HH * WW * CC];   // [b][y][x][c]

// ---------------------------------------------------------------------------
// PTX helpers (sm_80-era; compile on compute_103)
// ---------------------------------------------------------------------------
__device__ __forceinline__ uint32_t smem_u32(const void* p) {
    uint32_t a;
    asm("{ .reg .u64 t; cvta.to.shared.u64 t, %1; cvt.u32.u64 %0, t; }" : "=r"(a) : "l"(p));
    return a;
}
__device__ __forceinline__ void cpa16(uint32_t dst, const void* src, uint32_t bytes) {
    asm volatile("cp.async.cg.shared.global [%0], [%1], 16, %2;"
                 :: "r"(dst), "l"(src), "r"(bytes) : "memory");
}
__device__ __forceinline__ void cpa_commit() {
    asm volatile("cp.async.commit_group;" ::: "memory");
}
__device__ __forceinline__ void cpa_wait1() {
    asm volatile("cp.async.wait_group 1;" ::: "memory");
}
__device__ __forceinline__ uint32_t swz(uint32_t off) { return off ^ ((off >> 3) & 0x70); }

__device__ __forceinline__ void ldsm_x4(uint32_t& r0, uint32_t& r1, uint32_t& r2, uint32_t& r3,
                                        uint32_t addr) {
    asm volatile("ldmatrix.sync.aligned.m8n8.x4.shared.b16 {%0,%1,%2,%3}, [%4];"
                 : "=r"(r0), "=r"(r1), "=r"(r2), "=r"(r3) : "r"(addr));
}
__device__ __forceinline__ void mma_fp16(float* d, const uint32_t* a, const uint32_t* b) {
    asm volatile(
        "mma.sync.aligned.m16n8k16.row.col.f32.f16.f16.f32 "
        "{%0,%1,%2,%3}, {%4,%5,%6,%7}, {%8,%9}, {%0,%1,%2,%3};"
        : "+f"(d[0]), "+f"(d[1]), "+f"(d[2]), "+f"(d[3])
        : "r"(a[0]), "r"(a[1]), "r"(a[2]), "r"(a[3]), "r"(b[0]), "r"(b[1]));
}

// ---------------------------------------------------------------------------
// Kernel 0: style
// ---------------------------------------------------------------------------
__global__ void style_kernel(const float* __restrict__ nf,
                             const float* __restrict__ mw,
                             const float* __restrict__ mb) {
    int b = blockIdx.x, c = threadIdx.x;
    const float* nfb = nf + b * ND;
    const float* mwc = mw + c * ND;
    float s = 0.f;
#pragma unroll
    for (int d = 0; d < ND; ++d) s += nfb[d] * mwc[d];
    g_style[b * CC + c] = s + mb[c];
}

// ---------------------------------------------------------------------------
// Kernel 1: modulate + demod weights -> fp16, layout [b][tap][oc][i]
// ---------------------------------------------------------------------------
__global__ void modw_kernel(const float* __restrict__ weight) {
    int o = blockIdx.x, b = blockIdx.y, i = threadIdx.x;
    const float scale = 1.0f / 48.0f;
    float s = g_style[b * CC + i] * scale;
    const float* wp = weight + (o * CC + i) * 9;
    float v[9];
    float sq = 0.f;
#pragma unroll
    for (int k = 0; k < 9; ++k) { v[k] = wp[k] * s; sq += v[k] * v[k]; }

    __shared__ float red[8];
#pragma unroll
    for (int off = 16; off; off >>= 1) sq += __shfl_xor_sync(0xffffffffu, sq, off);
    if ((threadIdx.x & 31) == 0) red[threadIdx.x >> 5] = sq;
    __syncthreads();
    if (threadIdx.x < 8) {
        float t = red[threadIdx.x];
#pragma unroll
        for (int off = 4; off; off >>= 1) t += __shfl_xor_sync(0xffu, t, off);
        if (threadIdx.x == 0) red[0] = t;
    }
    __syncthreads();
    float demod = rsqrtf(red[0] + 1e-8f);
#pragma unroll
    for (int k = 0; k < 9; ++k) {
        size_t idx = ((size_t)((b * 9 + k) * CC) + o) * CC + i;
        g_Af[idx] = __float2half(v[k] * demod);
    }
}

// ---------------------------------------------------------------------------
// Kernel 2: fea NCHW -> [b][y][x][c] fp16
// ---------------------------------------------------------------------------
__global__ __launch_bounds__(256)
void tsplit_kernel(const float* __restrict__ fea) {
    int y = blockIdx.x, b = blockIdx.y;
    __shared__ float t[64][129];
    for (int cc = 0; cc < 4; ++cc) {
#pragma unroll
        for (int k = 0; k < 32; ++k) {
            int idx = threadIdx.x + k * 256;
            int cs = idx >> 7, x = idx & 127;
            t[cs][x] = fea[(((size_t)(b * CC + cc * 64 + cs)) * HH + y) * WW + x];
        }
        __syncthreads();
#pragma unroll
        for (int k = 0; k < 32; ++k) {
            int idx = threadIdx.x + k * 256;
            int c2 = idx & 63, x = idx >> 6;
            size_t o = ((size_t)((b * HH + y) * WW + x)) * CC + cc * 64 + c2;
            g_Ff[o] = __float2half(t[c2][x]);
        }
        __syncthreads();
    }
}

// ---------------------------------------------------------------------------
// Kernel 3: implicit-GEMM conv via mma.sync, fp16 operands, f32 accum.
// grid (y=128, b=8) = 1024 CTAs; CTA = 256 oc x 128 px; 256 threads,
// 8 warps (4M x 2N), warp tile 64x64: per kk 8 LDSM.x4 -> 32 HMMA (ratio 4).
// 36 K-steps (9 taps x 4 chunks of 64 ch); 3-stage ring of 48KB; 1 barrier/step.
// Stage: A@0 (32KB: 256 rows x 128B) B@32K (16KB: 128 rows x 128B), SW128.
// ---------------------------------------------------------------------------
#define NSTAGE 3
#define STAGE_BYTES 49152
#define SMEM_TOTAL (NSTAGE * STAGE_BYTES)

__global__ __launch_bounds__(256, 1)
void gemm_kernel(float* __restrict__ out) {
    extern __shared__ char smem[];
    const uint32_t sb = smem_u32(smem);
    const int tid  = threadIdx.x;
    const int lane = tid & 31;
    const int wid  = tid >> 5;
    const int warpM = wid >> 1;   // 0..3 (64 oc rows each)
    const int warpN = wid & 1;    // 0..1 (64 px cols each)
    const int y = blockIdx.x, b = blockIdx.y;

    // ---- producer assignment ----
    // every thread: A row tid (8 cpa16) + B half-row (4 cpa16) -> 12 each.
    const int bRow = tid >> 1;          // 0..127 pixel
    const int bHalf = tid & 1;          // 64B half
    const size_t aRowBase = ((size_t)(b * 9) * CC + tid) * CC;

    auto issue = [&](int step, int buf) {
        const int tap = step >> 2, ck = step & 3;
        const uint32_t stg = sb + (uint32_t)buf * STAGE_BYTES;
        // A row
        const __half* srcA = g_Af + aRowBase + (size_t)tap * CC * CC + ck * 64;
#pragma unroll
        for (int j = 0; j < 8; ++j)
            cpa16(stg + swz((uint32_t)tid * 128u + j * 16u), srcA + j * 8, 16u);
        // B half-row
        const int yy = y + tap / 3 - 1;
        const int xx = bRow + tap % 3 - 1;
        const bool bv = (yy >= 0 && yy < HH && xx >= 0 && xx < WW);
        const size_t boff = ((size_t)((b * HH + (bv ? yy : 0)) * WW + (bv ? xx : 0))) * CC
                            + ck * 64 + bHalf * 32;
        const __half* srcB = g_Ff + boff;
        const uint32_t bsz = bv ? 16u : 0u;
#pragma unroll
        for (int j = 0; j < 4; ++j)
            cpa16(stg + 32768u + swz((uint32_t)bRow * 128u + bHalf * 64u + j * 16u),
                  srcB + j * 8, bsz);
    };

    // ---- consumer address bases (pre-swizzle offsets within a stage) ----
    // A (x4): row = warpM*64 + m*16 + (lane&15); col16B = (lane>>4)
    const uint32_t aRowB = ((uint32_t)warpM * 64u + (lane & 15)) * 128u + ((lane >> 4) * 16u);
    // B (x4, 2 n-tiles per load): row = warpN*64 + np*16 + (lane>>4)*8 + (lane&7)
    const uint32_t bRowB = ((uint32_t)warpN * 64u + (lane >> 4) * 8u + (lane & 7)) * 128u
                           + (((lane >> 3) & 1) * 16u);

    float acc[4][8][4];
#pragma unroll
    for (int m = 0; m < 4; ++m)
#pragma unroll
        for (int n = 0; n < 8; ++n)
#pragma unroll
            for (int i = 0; i < 4; ++i) acc[m][n][i] = 0.f;

    // prologue: stages 0,1 in flight
    issue(0, 0); cpa_commit();
    issue(1, 1); cpa_commit();

#pragma unroll 1
    for (int s = 0; s < 36; ++s) {
        cpa_wait1();          // this thread's stage-s copies complete
        __syncthreads();      // all threads' copies visible; step s-1 reads done
        // producer writes buffer (s+2)%3 == (s-1)%3: safe only after the barrier
        if (s + 2 < 36) issue(s + 2, (s + 2) % NSTAGE);
        cpa_commit();

        const uint32_t stg = sb + (uint32_t)(s % NSTAGE) * STAGE_BYTES;

#pragma unroll
        for (int kk = 0; kk < 4; ++kk) {
            uint32_t A[4][4], B[4][4];
#pragma unroll
            for (int np = 0; np < 4; ++np) {
                const uint32_t off = swz(bRowB + (uint32_t)np * 2048u + (uint32_t)kk * 32u);
                ldsm_x4(B[np][0], B[np][1], B[np][2], B[np][3], stg + 32768u + off);
            }
#pragma unroll
            for (int m = 0; m < 4; ++m) {
                const uint32_t off = swz(aRowB + (uint32_t)m * 2048u + (uint32_t)kk * 32u);
                ldsm_x4(A[m][0], A[m][1], A[m][2], A[m][3], stg + off);
            }
#pragma unroll
            for (int m = 0; m < 4; ++m)
#pragma unroll
                for (int n = 0; n < 8; ++n)
                    mma_fp16(acc[m][n], A[m], &B[n >> 1][(n & 1) * 2]);
        }
    }

    // ---- epilogue ----
    const int r0 = warpM * 64 + (lane >> 2);
    const int xc = warpN * 64 + (lane & 3) * 2;
#pragma unroll
    for (int m = 0; m < 4; ++m) {
#pragma unroll
        for (int n = 0; n < 8; ++n) {
            float* p0 = out + (((size_t)(b * CC + r0 + m * 16) * HH + y) * WW) + xc + n * 8;
            float* p1 = p0 + (size_t)8 * HH * WW;
            *(float2*)p0 = make_float2(acc[m][n][0], acc[m][n][1]);
            *(float2*)p1 = make_float2(acc[m][n][2], acc[m][n][3]);
        }
    }
}

// ---------------------------------------------------------------------------
extern "C" void kernel_launch(void* const* d_in, const int* in_sizes, int n_in,
                              void* d_out, int out_size) {
    const float* fea    = (const float*)d_in[0];
    const float* nf     = (const float*)d_in[1];
    const float* mw     = (const float*)d_in[2];
    const float* mb     = (const float*)d_in[3];
    const float* weight = (const float*)d_in[4];
    float* out = (float*)d_out;

    cudaFuncSetAttribute(gemm_kernel, cudaFuncAttributeMaxDynamicSharedMemorySize, SMEM_TOTAL);

    style_kernel<<<BB, CC>>>(nf, mw, mb);
    modw_kernel<<<dim3(CC, BB), CC>>>(weight);
    tsplit_kernel<<<dim3(HH, BB), 256>>>(fea);
    gemm_kernel<<<dim3(HH, BB), 256, SMEM_TOTAL>>>(out);
}